// round 16
// baseline (speedup 1.0000x reference)
#include <cuda_runtime.h>

#define N_ATOMS 6144
#define FEAT    128
#define KE_KCAL 332.0637
#define MT 256                         // macro-tile side
#define GM (N_ATOMS / MT)              // 24
#define NTRI (GM * (GM + 1) / 2)       // 300 macro-tiles
#define NBLK (4 * NTRI)                // 1200 blocks (j-quarters)
#define JS 64                          // j's per block
#define TB 128                         // threads per block (2 i-atoms each)
#define CL 56.25f                      // clamp == switch threshold

__device__ float  g_pred[N_ATOMS];
__device__ float  g_q[N_ATOMS];
__device__ float4 g_p[N_ATOMS];        // x, y, z, sq
__device__ double g_bsum[384];         // per-block pred sums (k_charge)
__device__ double g_part[NBLK];        // per-block energy partials
__device__ int    g_count = 0;         // last-block-out counter (self-resetting)

// Single-instruction MUFU.RSQ.
__device__ __forceinline__ float rsq(float x) {
    float y;
    asm("rsqrt.approx.f32 %0, %1;" : "=f"(y) : "f"(x));
    return y;
}
// Packed f32x2 helpers (FFMA2-class ops exist on sm_103a only via PTX).
__device__ __forceinline__ unsigned long long pk(float lo, float hi) {
    unsigned long long r;
    asm("mov.b64 %0, {%1, %2};" : "=l"(r)
        : "r"(__float_as_uint(lo)), "r"(__float_as_uint(hi)));
    return r;
}
__device__ __forceinline__ void upk(unsigned long long v, float& lo, float& hi) {
    unsigned int a, b;
    asm("mov.b64 {%0, %1}, %2;" : "=r"(a), "=r"(b) : "l"(v));
    lo = __uint_as_float(a); hi = __uint_as_float(b);
}
__device__ __forceinline__ unsigned long long mul2(unsigned long long a, unsigned long long b) {
    unsigned long long r;
    asm("mul.rn.f32x2 %0, %1, %2;" : "=l"(r) : "l"(a), "l"(b));
    return r;
}
__device__ __forceinline__ unsigned long long add2(unsigned long long a, unsigned long long b) {
    unsigned long long r;
    asm("add.rn.f32x2 %0, %1, %2;" : "=l"(r) : "l"(a), "l"(b));
    return r;
}
__device__ __forceinline__ unsigned long long fma2(unsigned long long a, unsigned long long b,
                                                   unsigned long long c) {
    unsigned long long r;
    asm("fma.rn.f32x2 %0, %1, %2, %3;" : "=l"(r) : "l"(a), "l"(b), "l"(c));
    return r;
}

// ---------------------------------------------------------------------------
// Kernel 1: pred[i] = f[i].w + z_table[z[i]]  (2 atoms per warp for MLP)
// ---------------------------------------------------------------------------
__global__ __launch_bounds__(256) void k_charge(
    const float4* __restrict__ f4, const int* __restrict__ z,
    const float4* __restrict__ w4, const float* __restrict__ ztab)
{
    __shared__ double bsum[8];
    int tid   = threadIdx.x;
    int gwarp = (blockIdx.x * 256 + tid) >> 5;
    int lane  = tid & 31;
    int a0 = gwarp * 2, a1 = a0 + 1;
    float4 va = f4[(size_t)a0 * (FEAT / 4) + lane];
    float4 vb = f4[(size_t)a1 * (FEAT / 4) + lane];
    float4 wv = w4[lane];
    float s0 = fmaf(va.w, wv.w, fmaf(va.z, wv.z, fmaf(va.y, wv.y, va.x * wv.x)));
    float s1 = fmaf(vb.w, wv.w, fmaf(vb.z, wv.z, fmaf(vb.y, wv.y, vb.x * wv.x)));
#pragma unroll
    for (int o = 16; o; o >>= 1) {
        s0 += __shfl_xor_sync(0xffffffffu, s0, o);
        s1 += __shfl_xor_sync(0xffffffffu, s1, o);
    }
    if (lane == 0) {
        float p0 = s0 + ztab[z[a0]];
        float p1 = s1 + ztab[z[a1]];
        g_pred[a0] = p0;
        g_pred[a1] = p1;
        bsum[tid >> 5] = (double)p0 + (double)p1;
    }
    __syncthreads();
    if (tid == 0) {
        double t = 0.0;
#pragma unroll
        for (int k = 0; k < 8; k++) t += bsum[k];
        g_bsum[blockIdx.x] = t;
    }
}

// ---------------------------------------------------------------------------
// Kernel 2: every block re-reduces g_bsum identically (deterministic),
//           computes correction, then q + packed {x,y,z,sq}.
// ---------------------------------------------------------------------------
__global__ __launch_bounds__(256) void k_q(
    const float* __restrict__ xyz, const float* __restrict__ tc,
    float* __restrict__ q_out)
{
    __shared__ double ws[8];
    __shared__ float  s_corr;
    int tid = threadIdx.x;

    double s = g_bsum[tid] + ((tid < 128) ? g_bsum[tid + 256] : 0.0);
#pragma unroll
    for (int o = 16; o; o >>= 1)
        s += __shfl_xor_sync(0xffffffffu, s, o);
    if ((tid & 31) == 0) ws[tid >> 5] = s;
    __syncthreads();
    if (tid == 0) {
        double tot = 0.0;
#pragma unroll
        for (int k = 0; k < 8; k++) tot += ws[k];
        s_corr = (float)(((double)tc[0] - tot) / (double)N_ATOMS);
    }
    __syncthreads();

    int i = blockIdx.x * 256 + tid;
    float q = g_pred[i] + s_corr;
    g_q[i] = q;
    q_out[i] = q;
    float x = xyz[3 * i + 0], y = xyz[3 * i + 1], zc = xyz[3 * i + 2];
    // EXACT fma ordering reused in k_pairs so the i==j diagonal cancels to 0.
    float sq = fmaf(zc, zc, fmaf(y, y, x * x));
    g_p[i] = make_float4(x, y, zc, sq);
}

// ---------------------------------------------------------------------------
// Dummy kernel: aligns the ncu capture (4th launch) onto k_pairs.
// ---------------------------------------------------------------------------
__global__ void k_dummy() {}

// ---------------------------------------------------------------------------
// Fixup for one chain: walk rare-pair bits (64-bit mask), remove the clamped
// bogus term (recomputed bitwise-identically) and add the reference term.
// ---------------------------------------------------------------------------
__device__ __forceinline__ void fixup(
    unsigned long long m, float4 pi, const float4* sp4, const float* sqv,
    float& acc)
{
    while (m) {
        int b = __ffsll(m) - 1;
        m &= m - 1;
        float4 pj = sp4[b];
        float dot = fmaf(pi.z, pj.z, fmaf(pi.y, pj.y, pi.x * pj.x));
        float r2  = fmaf(-2.f, dot, pi.w + pj.w);
        acc = fmaf(-sqv[b], rsq(fmaxf(r2, CL)), acc);  // remove bogus
        if (r2 > 0.f) {                                 // excludes diagonal/neg
            float term;
            if (r2 <= 6.25f) {
                term = rsq(r2 + 1.f);                   // fs == 1
            } else {
                float ir  = rsq(r2);
                float r   = r2 * ir;
                float arg = (r - 2.5f) * 0.2f;
                float su  = __expf(-__fdividef(1.f, 1.f - arg));
                float sd  = __expf(-__fdividef(1.f, arg));
                float fs  = __fdividef(su, su + sd);
                term = fmaf(fs, rsq(r2 + 1.f), (1.f - fs) * ir);
            }
            acc = fmaf(sqv[b], term, acc);
        }
    }
}

// ---------------------------------------------------------------------------
// Kernel 3: pairwise energy. 256x256 triangular macro-tiles (300) x 4
// j-quarter blocks (1200 x 128 threads). Each thread owns TWO i-atoms packed
// into f32x2 lanes; j-data is pre-duplicated in shared as packed broadcasts,
// so the inner loop is 5 LDS.64 + 5 packed fp ops + scalar clamp/classify/
// MUFU per 2 pairs. 64-bit rare-pair masks, one fixup pass after the loop.
// Off-diagonal macro-tiles weighted 2x.
// ---------------------------------------------------------------------------
__global__ __launch_bounds__(TB) void k_pairs(float* __restrict__ out)
{
    __shared__ unsigned long long sx2[JS], sy2[JS], sz2[JS], sw2[JS], sq2[JS];
    __shared__ float4 sp4[JS];
    __shared__ float  sqv[JS];
    __shared__ double wsum[TB / 32];
    __shared__ int    s_last;

    int tid = threadIdx.x;

    int tile = blockIdx.x >> 2;
    int quar = blockIdx.x & 3;

    // linear macro-tile id -> (bx, by), bx <= by  (24x24 triangle)
    int rem = tile, by = 0;
    while (rem > by) { rem -= by + 1; by++; }
    int bx = rem;

    int i0 = bx * MT + tid;            // chain A atom
    int i1 = i0 + TB;                  // chain B atom
    int j0 = by * MT + quar * JS;

    if (tid < JS) {
        float4 p = g_p[j0 + tid];
        float  q = g_q[j0 + tid];
        sp4[tid] = p;
        sqv[tid] = q;
        sx2[tid] = pk(p.x, p.x);
        sy2[tid] = pk(p.y, p.y);
        sz2[tid] = pk(p.z, p.z);
        sw2[tid] = pk(p.w, p.w);
        sq2[tid] = pk(q, q);
    }
    __syncthreads();

    float4 pa = g_p[i0];
    float4 pb = g_p[i1];
    float  qa = g_q[i0];
    float  qb = g_q[i1];

    unsigned long long pix2 = pk(pa.x, pb.x);
    unsigned long long piy2 = pk(pa.y, pb.y);
    unsigned long long piz2 = pk(pa.z, pb.z);
    unsigned long long piw2 = pk(pa.w, pb.w);
    unsigned long long n2   = pk(-2.f, -2.f);
    unsigned long long acc2 = pk(0.f, 0.f);
    unsigned long long ma = 0, mb = 0;

#pragma unroll
    for (int j = 0; j < JS; j++) {
        unsigned long long xj2 = sx2[j];
        unsigned long long yj2 = sy2[j];
        unsigned long long zj2 = sz2[j];
        unsigned long long wj2 = sw2[j];
        unsigned long long qj2 = sq2[j];
        unsigned long long d2  = mul2(pix2, xj2);
        d2 = fma2(piy2, yj2, d2);
        d2 = fma2(piz2, zj2, d2);                 // dot, same order as fixup
        unsigned long long s2  = add2(piw2, wj2); // pi.w + pj.w
        unsigned long long r22 = fma2(n2, d2, s2);
        float ra, rb;
        upk(r22, ra, rb);
        float rca = fmaxf(ra, CL);
        float rcb = fmaxf(rb, CL);
        if (ra < CL) ma |= 1ull << j;             // predicated OR, no branch
        if (rb < CL) mb |= 1ull << j;
        unsigned long long i2 = pk(rsq(rca), rsq(rcb));
        acc2 = fma2(qj2, i2, acc2);               // q_j / r, every pair
    }

    float accA, accB;
    upk(acc2, accA, accB);
    fixup(ma, pa, sp4, sqv, accA);
    fixup(mb, pb, sp4, sqv, accB);

    double a = (double)(accA * qa) + (double)(accB * qb);
    if (bx != by) a *= 2.0;

    int lane = tid & 31, wid = tid >> 5;
#pragma unroll
    for (int o = 16; o; o >>= 1)
        a += __shfl_xor_sync(0xffffffffu, a, o);
    if (lane == 0) wsum[wid] = a;
    __syncthreads();
    if (tid == 0) {
        double t = 0.0;
#pragma unroll
        for (int k = 0; k < TB / 32; k++) t += wsum[k];
        g_part[blockIdx.x] = t;
        __threadfence();
        int old = atomicAdd(&g_count, 1);
        s_last = (old == NBLK - 1);
    }
    __syncthreads();

    if (s_last) {                          // last block: final reduction
        __threadfence();
        double s = 0.0;
        for (int k = tid; k < NBLK; k += TB)   // fixed order -> deterministic
            s += g_part[k];
#pragma unroll
        for (int o = 16; o; o >>= 1)
            s += __shfl_xor_sync(0xffffffffu, s, o);
        if (lane == 0) wsum[wid] = s;
        __syncthreads();
        if (tid == 0) {
            double tot = 0.0;
#pragma unroll
            for (int k = 0; k < TB / 32; k++) tot += wsum[k];
            out[0] = (float)(KE_KCAL * 0.5 * tot);
            g_count = 0;                   // reset for next graph replay
        }
    }
}

// ---------------------------------------------------------------------------
extern "C" void kernel_launch(void* const* d_in, const int* in_sizes, int n_in,
                              void* d_out, int out_size)
{
    const float* f    = (const float*)d_in[0];
    const int*   z    = (const int*)  d_in[1];
    const float* xyz  = (const float*)d_in[2];
    const float* tc   = (const float*)d_in[3];
    const float* w    = (const float*)d_in[4];
    const float* ztab = (const float*)d_in[5];
    float* out = (float*)d_out;

    k_charge<<<384, 256>>>((const float4*)f, z, (const float4*)w, ztab);
    k_q<<<N_ATOMS / 256, 256>>>(xyz, tc, out + 1);
    k_dummy<<<1, 32>>>();                  // profiling alignment (capture = launch #4)
    k_pairs<<<NBLK, TB>>>(out);
}

// round 17
// speedup vs baseline: 1.0900x; 1.0900x over previous
#include <cuda_runtime.h>

#define N_ATOMS 6144
#define FEAT    128
#define KE_KCAL 332.0637
#define MT 256                         // macro-tile side
#define GM (N_ATOMS / MT)              // 24
#define NTRI (GM * (GM + 1) / 2)       // 300 macro-tiles
#define NBLK (4 * NTRI)                // 1200 blocks (j-quarters)
#define JS 64                          // j's per block
#define TB 128                         // threads per block (2 i-atoms each)
#define CL 56.25f                      // clamp == switch threshold

__device__ float  g_pred[N_ATOMS];
__device__ float  g_q[N_ATOMS];
__device__ float4 g_p[N_ATOMS];        // x, y, z, sq
__device__ double g_bsum[192];         // per-block pred sums (k_charge)
__device__ double g_part[NBLK];        // per-block energy partials
__device__ int    g_count = 0;         // last-block-out counter (self-resetting)

// Single-instruction MUFU.RSQ.
__device__ __forceinline__ float rsq(float x) {
    float y;
    asm("rsqrt.approx.f32 %0, %1;" : "=f"(y) : "f"(x));
    return y;
}

// ---------------------------------------------------------------------------
// Kernel 1: pred[i] = f[i].w + z_table[z[i]]  (4 atoms per warp, MLP=4)
// ---------------------------------------------------------------------------
__global__ __launch_bounds__(256) void k_charge(
    const float4* __restrict__ f4, const int* __restrict__ z,
    const float4* __restrict__ w4, const float* __restrict__ ztab)
{
    __shared__ double bsum[8];
    int tid   = threadIdx.x;
    int gwarp = (blockIdx.x * 256 + tid) >> 5;
    int lane  = tid & 31;
    int a0 = gwarp * 4;
    float4 v0 = f4[(size_t)(a0 + 0) * (FEAT / 4) + lane];
    float4 v1 = f4[(size_t)(a0 + 1) * (FEAT / 4) + lane];
    float4 v2 = f4[(size_t)(a0 + 2) * (FEAT / 4) + lane];
    float4 v3 = f4[(size_t)(a0 + 3) * (FEAT / 4) + lane];
    float4 wv = w4[lane];
    float s0 = fmaf(v0.w, wv.w, fmaf(v0.z, wv.z, fmaf(v0.y, wv.y, v0.x * wv.x)));
    float s1 = fmaf(v1.w, wv.w, fmaf(v1.z, wv.z, fmaf(v1.y, wv.y, v1.x * wv.x)));
    float s2 = fmaf(v2.w, wv.w, fmaf(v2.z, wv.z, fmaf(v2.y, wv.y, v2.x * wv.x)));
    float s3 = fmaf(v3.w, wv.w, fmaf(v3.z, wv.z, fmaf(v3.y, wv.y, v3.x * wv.x)));
#pragma unroll
    for (int o = 16; o; o >>= 1) {
        s0 += __shfl_xor_sync(0xffffffffu, s0, o);
        s1 += __shfl_xor_sync(0xffffffffu, s1, o);
        s2 += __shfl_xor_sync(0xffffffffu, s2, o);
        s3 += __shfl_xor_sync(0xffffffffu, s3, o);
    }
    if (lane == 0) {
        float p0 = s0 + ztab[z[a0 + 0]];
        float p1 = s1 + ztab[z[a0 + 1]];
        float p2 = s2 + ztab[z[a0 + 2]];
        float p3 = s3 + ztab[z[a0 + 3]];
        g_pred[a0 + 0] = p0;
        g_pred[a0 + 1] = p1;
        g_pred[a0 + 2] = p2;
        g_pred[a0 + 3] = p3;
        bsum[tid >> 5] = ((double)p0 + (double)p1) + ((double)p2 + (double)p3);
    }
    __syncthreads();
    if (tid == 0) {
        double t = 0.0;
#pragma unroll
        for (int k = 0; k < 8; k++) t += bsum[k];
        g_bsum[blockIdx.x] = t;
    }
}

// ---------------------------------------------------------------------------
// Kernel 2: every block re-reduces g_bsum identically (deterministic),
//           computes correction, then q + packed {x,y,z,sq}.
// ---------------------------------------------------------------------------
__global__ __launch_bounds__(256) void k_q(
    const float* __restrict__ xyz, const float* __restrict__ tc,
    float* __restrict__ q_out)
{
    __shared__ double ws[8];
    __shared__ float  s_corr;
    int tid = threadIdx.x;

    double s = (tid < 192) ? g_bsum[tid] : 0.0;
#pragma unroll
    for (int o = 16; o; o >>= 1)
        s += __shfl_xor_sync(0xffffffffu, s, o);
    if ((tid & 31) == 0) ws[tid >> 5] = s;
    __syncthreads();
    if (tid == 0) {
        double tot = 0.0;
#pragma unroll
        for (int k = 0; k < 8; k++) tot += ws[k];
        s_corr = (float)(((double)tc[0] - tot) / (double)N_ATOMS);
    }
    __syncthreads();

    int i = blockIdx.x * 256 + tid;
    float q = g_pred[i] + s_corr;
    g_q[i] = q;
    q_out[i] = q;
    float x = xyz[3 * i + 0], y = xyz[3 * i + 1], zc = xyz[3 * i + 2];
    // EXACT fma ordering reused in k_pairs so the i==j diagonal cancels to 0.
    float sq = fmaf(zc, zc, fmaf(y, y, x * x));
    g_p[i] = make_float4(x, y, zc, sq);
}

// ---------------------------------------------------------------------------
// Dummy kernel: aligns the ncu capture (4th launch) onto k_pairs.
// ---------------------------------------------------------------------------
__global__ void k_dummy() {}

// ---------------------------------------------------------------------------
// Fixup for one chain: walk rare-pair bits (64-bit mask), remove the clamped
// bogus term (recomputed bitwise-identically) and add the reference term.
// ---------------------------------------------------------------------------
__device__ __forceinline__ void fixup(
    unsigned long long m, float4 pi, const float4* sp, const float* sqv,
    float& acc)
{
    while (m) {
        int b = __ffsll(m) - 1;
        m &= m - 1;
        float4 pj = sp[b];
        float dot = fmaf(pi.z, pj.z, fmaf(pi.y, pj.y, pi.x * pj.x));
        float r2  = fmaf(-2.f, dot, pi.w + pj.w);
        acc = fmaf(-sqv[b], rsq(fmaxf(r2, CL)), acc);  // remove bogus (bitwise)
        if (r2 > 0.f) {                                 // excludes diagonal/neg
            float term;
            if (r2 <= 6.25f) {
                term = rsq(r2 + 1.f);                   // fs == 1
            } else {
                float ir  = rsq(r2);
                float r   = r2 * ir;
                float arg = (r - 2.5f) * 0.2f;
                float su  = __expf(-__fdividef(1.f, 1.f - arg));
                float sd  = __expf(-__fdividef(1.f, arg));
                float fs  = __fdividef(su, su + sd);
                term = fmaf(fs, rsq(r2 + 1.f), (1.f - fs) * ir);
            }
            acc = fmaf(sqv[b], term, acc);
        }
    }
}

// ---------------------------------------------------------------------------
// Kernel 3: pairwise energy. R14 shape (300 macro-tiles x 4 j-quarters,
// 1200 x 128 threads, 2 i-atoms per thread) + EXPLICIT REGISTER DOUBLE-
// BUFFERING of j-data: sp[j+1]/sqv[j+1] are loaded into "next" registers
// before pair j is computed, decoupling the 29-cycle LDS latency from use.
// Off-diagonal macro-tiles weighted 2x.
// ---------------------------------------------------------------------------
__global__ __launch_bounds__(TB) void k_pairs(float* __restrict__ out)
{
    __shared__ float4 sp[JS];
    __shared__ float  sqv[JS];
    __shared__ double wsum[TB / 32];
    __shared__ int    s_last;

    int tid = threadIdx.x;

    int tile = blockIdx.x >> 2;
    int quar = blockIdx.x & 3;

    // linear macro-tile id -> (bx, by), bx <= by  (24x24 triangle)
    int rem = tile, by = 0;
    while (rem > by) { rem -= by + 1; by++; }
    int bx = rem;

    int i0 = bx * MT + tid;            // chain A atom
    int i1 = i0 + TB;                  // chain B atom
    int j0 = by * MT + quar * JS;

    if (tid < JS) {
        sp[tid]  = g_p[j0 + tid];
        sqv[tid] = g_q[j0 + tid];
    }
    __syncthreads();

    float4 pa = g_p[i0];
    float4 pb = g_p[i1];
    float  qa = g_q[i0];
    float  qb = g_q[i1];
    float  accA = 0.f, accB = 0.f;
    unsigned long long ma = 0, mb = 0;

    float4 pj = sp[0];
    float  qj = sqv[0];

#pragma unroll
    for (int j = 0; j < JS; j++) {
        // Prefetch next j (wraps harmlessly to 0 on the last iteration).
        float4 pjn = sp[(j + 1) & (JS - 1)];
        float  qjn = sqv[(j + 1) & (JS - 1)];

        float d0 = fmaf(pa.z, pj.z, fmaf(pa.y, pj.y, pa.x * pj.x));
        float d1 = fmaf(pb.z, pj.z, fmaf(pb.y, pj.y, pb.x * pj.x));
        float r0 = fmaf(-2.f, d0, pa.w + pj.w);
        float r1 = fmaf(-2.f, d1, pb.w + pj.w);
        if (r0 < CL) ma |= 1ull << j;          // predicated OR, no branch
        if (r1 < CL) mb |= 1ull << j;
        accA = fmaf(qj, rsq(fmaxf(r0, CL)), accA);   // q_j / r, every pair
        accB = fmaf(qj, rsq(fmaxf(r1, CL)), accB);

        pj = pjn;
        qj = qjn;
    }

    fixup(ma, pa, sp, sqv, accA);
    fixup(mb, pb, sp, sqv, accB);

    double a = (double)(accA * qa) + (double)(accB * qb);
    if (bx != by) a *= 2.0;

    int lane = tid & 31, wid = tid >> 5;
#pragma unroll
    for (int o = 16; o; o >>= 1)
        a += __shfl_xor_sync(0xffffffffu, a, o);
    if (lane == 0) wsum[wid] = a;
    __syncthreads();
    if (tid == 0) {
        double t = 0.0;
#pragma unroll
        for (int k = 0; k < TB / 32; k++) t += wsum[k];
        g_part[blockIdx.x] = t;
        __threadfence();
        int old = atomicAdd(&g_count, 1);
        s_last = (old == NBLK - 1);
    }
    __syncthreads();

    if (s_last) {                          // last block: final reduction
        __threadfence();
        double s = 0.0;
        for (int k = tid; k < NBLK; k += TB)   // fixed order -> deterministic
            s += g_part[k];
#pragma unroll
        for (int o = 16; o; o >>= 1)
            s += __shfl_xor_sync(0xffffffffu, s, o);
        if (lane == 0) wsum[wid] = s;
        __syncthreads();
        if (tid == 0) {
            double tot = 0.0;
#pragma unroll
            for (int k = 0; k < TB / 32; k++) tot += wsum[k];
            out[0] = (float)(KE_KCAL * 0.5 * tot);
            g_count = 0;                   // reset for next graph replay
        }
    }
}

// ---------------------------------------------------------------------------
extern "C" void kernel_launch(void* const* d_in, const int* in_sizes, int n_in,
                              void* d_out, int out_size)
{
    const float* f    = (const float*)d_in[0];
    const int*   z    = (const int*)  d_in[1];
    const float* xyz  = (const float*)d_in[2];
    const float* tc   = (const float*)d_in[3];
    const float* w    = (const float*)d_in[4];
    const float* ztab = (const float*)d_in[5];
    float* out = (float*)d_out;

    k_charge<<<192, 256>>>((const float4*)f, z, (const float4*)w, ztab);
    k_q<<<N_ATOMS / 256, 256>>>(xyz, tc, out + 1);
    k_dummy<<<1, 32>>>();                  // profiling alignment (capture = launch #4)
    k_pairs<<<NBLK, TB>>>(out);
}